// round 14
// baseline (speedup 1.0000x reference)
#include <cuda_runtime.h>
#include <math.h>
#include <stdint.h>

#define BB 4
#define TT 4096
#define CC 512
#define HD 64

#define BM 128           // q-tile rows per flash CTA
#define BN 64            // kv-tile rows
#define SPLIT 16         // max KV tiles per work item
#define QB_PER_B 32      // TT / BM
#define NITEMS_PER_B 80
#define NITEMS (BB * NITEMS_PER_B)   // 320
#define PAD 72           // flash smem row stride (u32), conflict-free LDS.64

// q/k stored head-PERMUTED tf32 bits (q pre-scaled by C^-0.5 * log2e).
// v stored per-64-token-tile TRANSPOSED [head][tok] tf32 bits (natural order).
__device__ uint32_t g_q[BB * TT * HD];
__device__ uint32_t g_k[BB * TT * HD];
__device__ uint32_t g_v[BB * TT * HD];

// pre-split W (hi/lo tf32 bits): [512 k][192 cols = Wk|Wq|Wv]
__device__ uint32_t g_wh[CC * 192];
__device__ uint32_t g_wl[CC * 192];

// split-KV partials
__device__ float g_pacc[BB * QB_PER_B * 4 * BM * HD];
__device__ float g_pm[BB * QB_PER_B * 4 * BM];
__device__ float g_pl[BB * QB_PER_B * 4 * BM];

// pair-permutation: maps j=8kk+c+4t -> 8kk+2c+t so (c, c+4) words are adjacent
__device__ __forceinline__ int permh(int j) {
    return (j & 0x38) | ((j & 3) << 1) | ((j >> 2) & 1);
}

__device__ __forceinline__ uint32_t f2tf(float f) {
    uint32_t u;
    asm("cvt.rna.tf32.f32 %0, %1;" : "=r"(u) : "f"(f));
    return u;
}

__device__ __forceinline__ void mma_tf32(float& d0, float& d1, float& d2, float& d3,
                                         uint32_t a0, uint32_t a1, uint32_t a2, uint32_t a3,
                                         uint32_t b0, uint32_t b1) {
    asm volatile(
        "mma.sync.aligned.m16n8k8.row.col.f32.tf32.tf32.f32 "
        "{%0,%1,%2,%3}, {%4,%5,%6,%7}, {%8,%9}, {%0,%1,%2,%3};"
        : "+f"(d0), "+f"(d1), "+f"(d2), "+f"(d3)
        : "r"(a0), "r"(a1), "r"(a2), "r"(a3), "r"(b0), "r"(b1));
}

__device__ __forceinline__ void tf_split(float v, uint32_t& hi, uint32_t& lo) {
    hi = f2tf(v);
    float hif = __uint_as_float(hi);
    lo = f2tf(v - hif);
}

__device__ __forceinline__ uint32_t smem_u32(const void* p) {
    return (uint32_t)__cvta_generic_to_shared(p);
}
__device__ __forceinline__ void cp_async16(uint32_t dst, const void* src) {
    asm volatile("cp.async.ca.shared.global [%0], [%1], 16;" :: "r"(dst), "l"(src));
}
__device__ __forceinline__ void cp_commit() {
    asm volatile("cp.async.commit_group;");
}
template <int N>
__device__ __forceinline__ void cp_wait() {
    asm volatile("cp.async.wait_group %0;" :: "n"(N));
}

// ---------------------------------------------------------------------------
// Prep: split W (Wk|Wq|Wv -> [512][192]) into hi/lo tf32 bits.
// ---------------------------------------------------------------------------
__global__ __launch_bounds__(256) void prep_kernel(const float* __restrict__ Wk,
                                                   const float* __restrict__ Wq,
                                                   const float* __restrict__ Wv) {
    int idx = blockIdx.x * 256 + threadIdx.x;       // float4 index, < 512*48
    if (idx >= CC * 48) return;
    int k = idx / 48;
    int c4 = (idx % 48) << 2;                       // 0..188
    const float* src;
    if (c4 < 64)       src = Wk + (size_t)k * HD + c4;
    else if (c4 < 128) src = Wq + (size_t)k * HD + (c4 - 64);
    else               src = Wv + (size_t)k * HD + (c4 - 128);
    float4 v = *(const float4*)src;
    uint4 uh, ul;
    tf_split(v.x, uh.x, ul.x);
    tf_split(v.y, uh.y, ul.y);
    tf_split(v.z, uh.z, ul.z);
    tf_split(v.w, uh.w, ul.w);
    *(uint4*)&g_wh[k * 192 + c4] = uh;
    *(uint4*)&g_wl[k * 192 + c4] = ul;
}

// ---------------------------------------------------------------------------
// Fused projection GEMM (2xTF32: ah*bh + ah*bl, W effectively exact):
// [16384x512] @ [512x192]
// ---------------------------------------------------------------------------
#define KC 32
#define PXS 36                // x raw row stride
#define PWS 200               // W hi/lo row stride
#define XRSZ (128 * PXS)      // 4608
#define WSZ (KC * PWS)        // 6400

__global__ __launch_bounds__(512, 1) void proj_kernel(const float* __restrict__ x) {
    extern __shared__ uint32_t psm[];
    uint32_t* xrb[2] = { psm, psm + XRSZ };
    uint32_t* whb[2] = { psm + 2 * XRSZ, psm + 2 * XRSZ + WSZ };
    uint32_t* wlb[2] = { psm + 2 * XRSZ + 2 * WSZ, psm + 2 * XRSZ + 3 * WSZ };

    const int row0 = blockIdx.x * 128;
    const int tid = threadIdx.x;
    const int w = tid >> 5;
    const int lane = tid & 31;
    const int g = lane >> 2;
    const int c = lane & 3;
    const int wr = (w & 3) * 32;      // warp row base (0,32,64,96)
    const int wc = (w >> 2) * 48;     // warp col base (0,48,96,144)

    auto load_chunk = [&](int ch, int bi) {
#pragma unroll
        for (int it = 0; it < 2; it++) {
            int f = tid + it * 512;
            int r = f >> 3, c4 = (f & 7) << 2;
            cp_async16(smem_u32(&xrb[bi][r * PXS + c4]),
                       &x[(size_t)(row0 + r) * CC + ch * KC + c4]);
        }
#pragma unroll
        for (int it = 0; it < 6; it++) {
            int f = tid + it * 512;
            if (f < 1536) {
                int r = f / 48, c4 = (f % 48) << 2;
                cp_async16(smem_u32(&whb[bi][r * PWS + c4]),
                           &g_wh[(size_t)(ch * KC + r) * 192 + c4]);
            } else {
                int f2 = f - 1536;
                int r = f2 / 48, c4 = (f2 % 48) << 2;
                cp_async16(smem_u32(&wlb[bi][r * PWS + c4]),
                           &g_wl[(size_t)(ch * KC + r) * 192 + c4]);
            }
        }
        cp_commit();
    };

    float acc[2][6][4];
#pragma unroll
    for (int mt = 0; mt < 2; mt++)
#pragma unroll
        for (int nb = 0; nb < 6; nb++)
#pragma unroll
            for (int i = 0; i < 4; i++) acc[mt][nb][i] = 0.f;

    load_chunk(0, 0);

#pragma unroll 1
    for (int ch = 0; ch < CC / KC; ch++) {
        const int bi = ch & 1;
        __syncthreads();
        if (ch + 1 < CC / KC) {
            load_chunk(ch + 1, bi ^ 1);
            cp_wait<1>();
        } else {
            cp_wait<0>();
        }
        __syncthreads();

        const uint32_t* xr = xrb[bi];
        const uint32_t* wh = whb[bi];
        const uint32_t* wl = wlb[bi];
#pragma unroll
        for (int kk = 0; kk < KC / 8; kk++) {
            uint32_t ah[2][4];
#pragma unroll
            for (int mt = 0; mt < 2; mt++) {
                int r = wr + 16 * mt;
                ah[mt][0] = f2tf(__uint_as_float(xr[(r + g) * PXS + 8 * kk + c]));
                ah[mt][1] = f2tf(__uint_as_float(xr[(r + g + 8) * PXS + 8 * kk + c]));
                ah[mt][2] = f2tf(__uint_as_float(xr[(r + g) * PXS + 8 * kk + c + 4]));
                ah[mt][3] = f2tf(__uint_as_float(xr[(r + g + 8) * PXS + 8 * kk + c + 4]));
            }
#pragma unroll
            for (int nb = 0; nb < 6; nb++) {
                int bcol = wc + 8 * nb + g;
                uint32_t bh0 = wh[(8 * kk + c) * PWS + bcol];
                uint32_t bh1 = wh[(8 * kk + c + 4) * PWS + bcol];
                uint32_t bl0 = wl[(8 * kk + c) * PWS + bcol];
                uint32_t bl1 = wl[(8 * kk + c + 4) * PWS + bcol];
#pragma unroll
                for (int mt = 0; mt < 2; mt++) {
                    mma_tf32(acc[mt][nb][0], acc[mt][nb][1], acc[mt][nb][2], acc[mt][nb][3],
                             ah[mt][0], ah[mt][1], ah[mt][2], ah[mt][3], bh0, bh1);
                    mma_tf32(acc[mt][nb][0], acc[mt][nb][1], acc[mt][nb][2], acc[mt][nb][3],
                             ah[mt][0], ah[mt][1], ah[mt][2], ah[mt][3], bl0, bl1);
                }
            }
        }
    }

    // ---- epilogue: permuted (q/k) and tile-transposed (v) tf32 stores ----
    const float qscale = rsqrtf((float)CC) * 1.44269504088896341f;
#pragma unroll
    for (int mt = 0; mt < 2; mt++) {
#pragma unroll
        for (int nb = 0; nb < 6; nb++) {
            int colg = wc + 8 * nb + 2 * c;
            int rg0 = row0 + wr + 16 * mt + g;
            int rg1 = rg0 + 8;
            float v0 = acc[mt][nb][0], v1 = acc[mt][nb][1];
            float v2 = acc[mt][nb][2], v3 = acc[mt][nb][3];
            if (colg < 64) {                  // K: head-permuted, token-major
                int p0 = permh(colg), p1 = permh(colg + 1);
                g_k[(size_t)rg0 * HD + p0] = f2tf(v0);
                g_k[(size_t)rg0 * HD + p1] = f2tf(v1);
                g_k[(size_t)rg1 * HD + p0] = f2tf(v2);
                g_k[(size_t)rg1 * HD + p1] = f2tf(v3);
            } else if (colg < 128) {          // Q: head-permuted, scaled
                int h = colg - 64;
                int p0 = permh(h), p1 = permh(h + 1);
                g_q[(size_t)rg0 * HD + p0] = f2tf(v0 * qscale);
                g_q[(size_t)rg0 * HD + p1] = f2tf(v1 * qscale);
                g_q[(size_t)rg1 * HD + p0] = f2tf(v2 * qscale);
                g_q[(size_t)rg1 * HD + p1] = f2tf(v3 * qscale);
            } else {                          // V: per-tile transposed [head][tok]
                int h0 = colg - 128;
                int tile = rg0 >> 6;          // rg1 in same tile
                int pt0 = rg0 & 63;
                int pt1 = rg1 & 63;
                size_t base = (size_t)tile * 4096;
                g_v[base + (size_t)h0 * 64 + pt0]       = f2tf(v0);
                g_v[base + (size_t)(h0 + 1) * 64 + pt0] = f2tf(v1);
                g_v[base + (size_t)h0 * 64 + pt1]       = f2tf(v2);
                g_v[base + (size_t)(h0 + 1) * 64 + pt1] = f2tf(v3);
            }
        }
    }
}

// ---------------------------------------------------------------------------
// Flash attention, tf32 mma, split-KV, cp.async double-buffered K/V.
// 4 warps x 32 rows each: every K/V B-fragment loaded once per warp and
// reused for 2 m-tiles (halves smem traffic vs 8x16 layout).
// ---------------------------------------------------------------------------
#define KVBUF (2 * 64 * PAD)

__global__ __launch_bounds__(128, 2) void flash_kernel() {
    extern __shared__ uint32_t smem[];
    uint32_t (*Ps)[PAD] = (uint32_t(*)[PAD])(smem + 2 * KVBUF);  // Q staging

    const int rr = NITEMS - 1 - blockIdx.x;
    const int b = rr / NITEMS_PER_B;
    const int r = rr - b * NITEMS_PER_B;
    int qb, sp;
    if (r < 8)       { qb = r;                 sp = 0; }
    else if (r < 24) { qb = 8 + (r - 8) / 2;   sp = (r - 8) & 1; }
    else if (r < 48) { qb = 16 + (r - 24) / 3; sp = (r - 24) % 3; }
    else             { qb = 24 + (r - 48) / 4; sp = (r - 48) & 3; }

    const int n_tiles = 2 * qb + 2;
    const int jb_lo = sp * SPLIT;
    const int jb_hi = min(jb_lo + SPLIT, n_tiles);

    const int tid = threadIdx.x;
    const int w = tid >> 5;          // warp 0..3, rows [32w, 32w+32)
    const int lane = tid & 31;
    const int g = lane >> 2;
    const int c = lane & 3;

    auto kv_load = [&](int jb, int bi) {
        const uint32_t* Kg = g_k + ((size_t)b * TT + (size_t)jb * BN) * HD;
        const uint32_t* Vg = g_v + ((size_t)b * TT + (size_t)jb * BN) * HD; // tile*4096
        uint32_t* Kd = smem + bi * KVBUF;
        uint32_t* Vd = Kd + 64 * PAD;
#pragma unroll
        for (int it = 0; it < 8; it++) {
            int f = tid + it * 128;
            int row = f >> 4, c4 = (f & 15) << 2;
            cp_async16(smem_u32(&Kd[row * PAD + c4]), &Kg[(size_t)row * HD + c4]);
            cp_async16(smem_u32(&Vd[row * PAD + c4]), &Vg[(size_t)row * HD + c4]);
        }
        cp_commit();
    };

    const uint32_t* Qg = g_q + ((size_t)b * TT + (size_t)qb * BM) * HD;
#pragma unroll
    for (int it = 0; it < 16; it++) {
        int f = tid + it * 128;
        int row = f >> 4, c4 = (f & 15) << 2;
        cp_async16(smem_u32(&Ps[row][c4]), &Qg[(size_t)row * HD + c4]);
    }
    cp_commit();
    kv_load(jb_lo, 0);
    cp_wait<1>();           // Q ready
    __syncthreads();

    float o[2][8][4];
#pragma unroll
    for (int mt = 0; mt < 2; mt++)
#pragma unroll
        for (int nb = 0; nb < 8; nb++)
#pragma unroll
            for (int i = 0; i < 4; i++) o[mt][nb][i] = 0.f;
    float mA[2] = {-INFINITY, -INFINITY}, mB[2] = {-INFINITY, -INFINITY};
    float lA[2] = {0.f, 0.f}, lB[2] = {0.f, 0.f};

#pragma unroll 1
    for (int jb = jb_lo; jb < jb_hi; jb++) {
        const int bi = (jb - jb_lo) & 1;
        __syncthreads();
        if (jb + 1 < jb_hi) {
            kv_load(jb + 1, bi ^ 1);
            cp_wait<1>();
        } else {
            cp_wait<0>();
        }
        __syncthreads();

        const uint32_t (*Ks)[PAD] = (const uint32_t(*)[PAD])(smem + bi * KVBUF);
        const uint32_t (*Vs)[PAD] = (const uint32_t(*)[PAD])(smem + bi * KVBUF + 64 * PAD);

        // ---- S = Q K^T (B-frag shared across both m-tiles) ----
        float s[2][8][4];
#pragma unroll
        for (int mt = 0; mt < 2; mt++)
#pragma unroll
            for (int nb = 0; nb < 8; nb++)
                s[mt][nb][0] = s[mt][nb][1] = s[mt][nb][2] = s[mt][nb][3] = 0.f;

#pragma unroll
        for (int kk = 0; kk < 8; kk++) {
            uint2 a00 = *(const uint2*)&Ps[32 * w + g][8 * kk + 2 * c];
            uint2 a01 = *(const uint2*)&Ps[32 * w + g + 8][8 * kk + 2 * c];
            uint2 a10 = *(const uint2*)&Ps[32 * w + 16 + g][8 * kk + 2 * c];
            uint2 a11 = *(const uint2*)&Ps[32 * w + 24 + g][8 * kk + 2 * c];
#pragma unroll
            for (int nb = 0; nb < 8; nb++) {
                uint2 ub = *(const uint2*)&Ks[8 * nb + g][8 * kk + 2 * c];
                mma_tf32(s[0][nb][0], s[0][nb][1], s[0][nb][2], s[0][nb][3],
                         a00.x, a01.x, a00.y, a01.y, ub.x, ub.y);
                mma_tf32(s[1][nb][0], s[1][nb][1], s[1][nb][2], s[1][nb][3],
                         a10.x, a11.x, a10.y, a11.y, ub.x, ub.y);
            }
        }

        if (jb >= n_tiles - 2) {          // causal mask (diagonal tiles)
            const int col0g = jb * BN + 2 * c;
#pragma unroll
            for (int mt = 0; mt < 2; mt++) {
                const int row0g = qb * BM + 32 * w + 16 * mt + g;
#pragma unroll
                for (int nb = 0; nb < 8; nb++) {
                    int cg = col0g + 8 * nb;
                    if (cg     > row0g)     s[mt][nb][0] = -INFINITY;
                    if (cg + 1 > row0g)     s[mt][nb][1] = -INFINITY;
                    if (cg     > row0g + 8) s[mt][nb][2] = -INFINITY;
                    if (cg + 1 > row0g + 8) s[mt][nb][3] = -INFINITY;
                }
            }
        }

        // ---- online softmax (base-2); P kept in registers as tf32 bits ----
#pragma unroll
        for (int mt = 0; mt < 2; mt++) {
            float mx0 = -INFINITY, mx1 = -INFINITY;
#pragma unroll
            for (int nb = 0; nb < 8; nb++) {
                mx0 = fmaxf(mx0, fmaxf(s[mt][nb][0], s[mt][nb][1]));
                mx1 = fmaxf(mx1, fmaxf(s[mt][nb][2], s[mt][nb][3]));
            }
#pragma unroll
            for (int off = 1; off <= 2; off <<= 1) {
                mx0 = fmaxf(mx0, __shfl_xor_sync(0xffffffffu, mx0, off));
                mx1 = fmaxf(mx1, __shfl_xor_sync(0xffffffffu, mx1, off));
            }
            float mn0 = fmaxf(mA[mt], mx0), mn1 = fmaxf(mB[mt], mx1);
            float a0 = exp2f(mA[mt] - mn0), a1 = exp2f(mB[mt] - mn1);
            mA[mt] = mn0; mB[mt] = mn1;

            float rs0 = 0.f, rs1 = 0.f;
#pragma unroll
            for (int nb = 0; nb < 8; nb++) {
                float p0 = exp2f(s[mt][nb][0] - mn0);
                float p1 = exp2f(s[mt][nb][1] - mn0);
                float p2 = exp2f(s[mt][nb][2] - mn1);
                float p3 = exp2f(s[mt][nb][3] - mn1);
                rs0 += p0 + p1; rs1 += p2 + p3;
                s[mt][nb][0] = __uint_as_float(f2tf(p0));
                s[mt][nb][1] = __uint_as_float(f2tf(p1));
                s[mt][nb][2] = __uint_as_float(f2tf(p2));
                s[mt][nb][3] = __uint_as_float(f2tf(p3));
            }
#pragma unroll
            for (int off = 1; off <= 2; off <<= 1) {
                rs0 += __shfl_xor_sync(0xffffffffu, rs0, off);
                rs1 += __shfl_xor_sync(0xffffffffu, rs1, off);
            }
            lA[mt] = lA[mt] * a0 + rs0;
            lB[mt] = lB[mt] * a1 + rs1;
#pragma unroll
            for (int nb = 0; nb < 8; nb++) {
                o[mt][nb][0] *= a0; o[mt][nb][1] *= a0;
                o[mt][nb][2] *= a1; o[mt][nb][3] *= a1;
            }
        }

        // ---- O += P V (B-frag shared across both m-tiles) ----
#pragma unroll
        for (int kk = 0; kk < 8; kk++) {
            uint32_t p00 = __float_as_uint(s[0][kk][0]);
            uint32_t p01 = __float_as_uint(s[0][kk][2]);
            uint32_t p02 = __float_as_uint(s[0][kk][1]);
            uint32_t p03 = __float_as_uint(s[0][kk][3]);
            uint32_t p10 = __float_as_uint(s[1][kk][0]);
            uint32_t p11 = __float_as_uint(s[1][kk][2]);
            uint32_t p12 = __float_as_uint(s[1][kk][1]);
            uint32_t p13 = __float_as_uint(s[1][kk][3]);
#pragma unroll
            for (int nb = 0; nb < 8; nb++) {
                uint2 uv = *(const uint2*)&Vs[8 * nb + g][8 * kk + 2 * c];
                mma_tf32(o[0][nb][0], o[0][nb][1], o[0][nb][2], o[0][nb][3],
                         p00, p01, p02, p03, uv.x, uv.y);
                mma_tf32(o[1][nb][0], o[1][nb][1], o[1][nb][2], o[1][nb][3],
                         p10, p11, p12, p13, uv.x, uv.y);
            }
        }
    }

    const int p = ((b * QB_PER_B + qb) << 2) + sp;
    float* pacc = g_pacc + (size_t)p * BM * HD;
#pragma unroll
    for (int mt = 0; mt < 2; mt++) {
        const int r0 = 32 * w + 16 * mt + g;
#pragma unroll
        for (int nb = 0; nb < 8; nb++) {
            *(float2*)&pacc[(size_t)r0 * HD + 8 * nb + 2 * c] =
                make_float2(o[mt][nb][0], o[mt][nb][1]);
            *(float2*)&pacc[(size_t)(r0 + 8) * HD + 8 * nb + 2 * c] =
                make_float2(o[mt][nb][2], o[mt][nb][3]);
        }
        if (c == 0) {
            g_pm[p * BM + r0] = mA[mt];     g_pm[p * BM + r0 + 8] = mB[mt];
            g_pl[p * BM + r0] = lA[mt];     g_pl[p * BM + r0 + 8] = lB[mt];
        }
    }
}

// ---------------------------------------------------------------------------
// Combine split partials -> output. Grid (128, 4): block = 32 rows x 64 cols.
// ---------------------------------------------------------------------------
__global__ __launch_bounds__(256) void combine_kernel(float* __restrict__ out) {
    __shared__ float wsm[4][32];
    __shared__ float linv[32];

    const int bq = blockIdx.x;                 // 0..127
    const int b = bq >> 5;
    const int qb = bq & 31;
    const int nS = qb / 8 + 1;                 // 1..4 splits
    const int yc = blockIdx.y;                 // row chunk 0..3 (32 rows each)
    const int tid = threadIdx.x;
    const int pbase = bq << 2;

    if (tid < 32) {
        int row = yc * 32 + tid;
        float M = -INFINITY;
#pragma unroll 4
        for (int s = 0; s < nS; s++)
            M = fmaxf(M, g_pm[(pbase + s) * BM + row]);
        float L = 0.f;
#pragma unroll 4
        for (int s = 0; s < nS; s++) {
            float wgt = exp2f(g_pm[(pbase + s) * BM + row] - M);
            wsm[s][tid] = wgt;
            L += g_pl[(pbase + s) * BM + row] * wgt;
        }
        linv[tid] = 1.0f / L;
    }
    __syncthreads();

    float* og = out + ((size_t)b * TT + (size_t)qb * BM) * HD;

#pragma unroll
    for (int e = 0; e < 2; e++) {
        int f = tid + e * 256;                 // 0..511 float4 slots
        int row_l = f >> 4;                    // 0..31
        int c4 = (f & 15) << 2;                // 0..60
        int row = yc * 32 + row_l;
        size_t off = (size_t)row * HD + c4;

        float4 sum = make_float4(0.f, 0.f, 0.f, 0.f);
#pragma unroll 4
        for (int s = 0; s < nS; s++) {
            float4 v = *(const float4*)&g_pacc[(size_t)(pbase + s) * BM * HD + off];
            float wgt = wsm[s][row_l];
            sum.x += v.x * wgt;
            sum.y += v.y * wgt;
            sum.z += v.z * wgt;
            sum.w += v.w * wgt;
        }
        float li = linv[row_l];
        sum.x *= li; sum.y *= li; sum.z *= li; sum.w *= li;
        *(float4*)&og[off] = sum;
    }
}

// ---------------------------------------------------------------------------
extern "C" void kernel_launch(void* const* d_in, const int* in_sizes, int n_in,
                              void* d_out, int out_size) {
    const float* x  = (const float*)d_in[0];
    const float* Wk = (const float*)d_in[1];
    const float* Wq = (const float*)d_in[2];
    const float* Wv = (const float*)d_in[3];
    float* out = (float*)d_out;
    (void)in_sizes; (void)n_in; (void)out_size;

    const int proj_smem = (2 * XRSZ + 4 * WSZ) * (int)sizeof(uint32_t);     // 139264
    const int flash_smem = (2 * KVBUF + 128 * PAD) * (int)sizeof(uint32_t); // 110592
    cudaFuncSetAttribute(proj_kernel,
                         cudaFuncAttributeMaxDynamicSharedMemorySize, proj_smem);
    cudaFuncSetAttribute(flash_kernel,
                         cudaFuncAttributeMaxDynamicSharedMemorySize, flash_smem);

    prep_kernel<<<96, 256>>>(Wk, Wq, Wv);
    proj_kernel<<<128, 512, proj_smem>>>(x);
    flash_kernel<<<NITEMS, 128, flash_smem>>>();
    combine_kernel<<<dim3(128, 4), 256>>>(out);
}

// round 15
// speedup vs baseline: 1.3187x; 1.3187x over previous
#include <cuda_runtime.h>
#include <cuda_fp16.h>
#include <math.h>
#include <stdint.h>

#define BB 4
#define TT 4096
#define CC 512
#define HD 64

#define BM 128           // q-tile rows per flash CTA
#define BN 64            // kv-tile rows
#define SPLIT 16         // max KV tiles per work item
#define QB_PER_B 32      // TT / BM
#define NITEMS_PER_B 80
#define NITEMS (BB * NITEMS_PER_B)   // 320

// fp16 packed storage (2 elems per u32):
// q/k: [tok][head-pair permuted]  (q pre-scaled by C^-0.5 * log2e)
// v:   per-64-tok tile, [head][tok-pair permuted]
__device__ uint32_t g_q[BB * TT * HD / 2];
__device__ uint32_t g_k[BB * TT * HD / 2];
__device__ uint32_t g_v[BB * TT * HD / 2];

// pre-split W (hi/lo tf32 bits): [512 k][192 cols = Wk|Wq|Wv]
__device__ uint32_t g_wh[CC * 192];
__device__ uint32_t g_wl[CC * 192];

// split-KV partials
__device__ float g_pacc[BB * QB_PER_B * 4 * BM * HD];
__device__ float g_pm[BB * QB_PER_B * 4 * BM];
__device__ float g_pl[BB * QB_PER_B * 4 * BM];

// pair-index permutation (32 pairs): maps (8a+c, 8a+c+4) -> (8a+2c, 8a+2c+1)
__device__ __forceinline__ int permp(int p) {
    return (p & 0x18) | ((p & 3) << 1) | ((p >> 2) & 1);
}

__device__ __forceinline__ uint32_t f2tf(float f) {
    uint32_t u;
    asm("cvt.rna.tf32.f32 %0, %1;" : "=r"(u) : "f"(f));
    return u;
}

__device__ __forceinline__ uint32_t packh2(float lo, float hi) {
    __half2 h = __floats2half2_rn(lo, hi);
    return *(uint32_t*)&h;
}

__device__ __forceinline__ void mma_tf32(float& d0, float& d1, float& d2, float& d3,
                                         uint32_t a0, uint32_t a1, uint32_t a2, uint32_t a3,
                                         uint32_t b0, uint32_t b1) {
    asm volatile(
        "mma.sync.aligned.m16n8k8.row.col.f32.tf32.tf32.f32 "
        "{%0,%1,%2,%3}, {%4,%5,%6,%7}, {%8,%9}, {%0,%1,%2,%3};"
        : "+f"(d0), "+f"(d1), "+f"(d2), "+f"(d3)
        : "r"(a0), "r"(a1), "r"(a2), "r"(a3), "r"(b0), "r"(b1));
}

__device__ __forceinline__ void mma_f16(float& d0, float& d1, float& d2, float& d3,
                                        uint32_t a0, uint32_t a1, uint32_t a2, uint32_t a3,
                                        uint32_t b0, uint32_t b1) {
    asm volatile(
        "mma.sync.aligned.m16n8k16.row.col.f32.f16.f16.f32 "
        "{%0,%1,%2,%3}, {%4,%5,%6,%7}, {%8,%9}, {%0,%1,%2,%3};"
        : "+f"(d0), "+f"(d1), "+f"(d2), "+f"(d3)
        : "r"(a0), "r"(a1), "r"(a2), "r"(a3), "r"(b0), "r"(b1));
}

__device__ __forceinline__ void tf_split(float v, uint32_t& hi, uint32_t& lo) {
    hi = f2tf(v);
    float hif = __uint_as_float(hi);
    lo = f2tf(v - hif);
}

__device__ __forceinline__ uint32_t smem_u32(const void* p) {
    return (uint32_t)__cvta_generic_to_shared(p);
}
__device__ __forceinline__ void cp_async16(uint32_t dst, const void* src) {
    asm volatile("cp.async.ca.shared.global [%0], [%1], 16;" :: "r"(dst), "l"(src));
}
__device__ __forceinline__ void cp_commit() {
    asm volatile("cp.async.commit_group;");
}
template <int N>
__device__ __forceinline__ void cp_wait() {
    asm volatile("cp.async.wait_group %0;" :: "n"(N));
}

// ---------------------------------------------------------------------------
// Prep: split W (Wk|Wq|Wv -> [512][192]) into hi/lo tf32 bits.
// ---------------------------------------------------------------------------
__global__ __launch_bounds__(256) void prep_kernel(const float* __restrict__ Wk,
                                                   const float* __restrict__ Wq,
                                                   const float* __restrict__ Wv) {
    int idx = blockIdx.x * 256 + threadIdx.x;       // float4 index, < 512*48
    if (idx >= CC * 48) return;
    int k = idx / 48;
    int c4 = (idx % 48) << 2;                       // 0..188
    const float* src;
    if (c4 < 64)       src = Wk + (size_t)k * HD + c4;
    else if (c4 < 128) src = Wq + (size_t)k * HD + (c4 - 64);
    else               src = Wv + (size_t)k * HD + (c4 - 128);
    float4 v = *(const float4*)src;
    uint4 uh, ul;
    tf_split(v.x, uh.x, ul.x);
    tf_split(v.y, uh.y, ul.y);
    tf_split(v.z, uh.z, ul.z);
    tf_split(v.w, uh.w, ul.w);
    *(uint4*)&g_wh[k * 192 + c4] = uh;
    *(uint4*)&g_wl[k * 192 + c4] = ul;
}

// ---------------------------------------------------------------------------
// Fused projection GEMM (2xTF32: ah*bh + ah*bl): [16384x512] @ [512x192]
// Epilogue writes fp16-packed q/k/v.
// ---------------------------------------------------------------------------
#define KC 32
#define PXS 36                // x raw row stride
#define PWS 200               // W hi/lo row stride
#define XRSZ (128 * PXS)      // 4608
#define WSZ (KC * PWS)        // 6400

__global__ __launch_bounds__(512, 1) void proj_kernel(const float* __restrict__ x) {
    extern __shared__ uint32_t psm[];
    uint32_t* xrb[2] = { psm, psm + XRSZ };
    uint32_t* whb[2] = { psm + 2 * XRSZ, psm + 2 * XRSZ + WSZ };
    uint32_t* wlb[2] = { psm + 2 * XRSZ + 2 * WSZ, psm + 2 * XRSZ + 3 * WSZ };

    const int row0 = blockIdx.x * 128;
    const int tid = threadIdx.x;
    const int w = tid >> 5;
    const int lane = tid & 31;
    const int g = lane >> 2;
    const int c = lane & 3;
    const int wr = (w & 3) * 32;      // warp row base (0,32,64,96)
    const int wc = (w >> 2) * 48;     // warp col base (0,48,96,144)

    auto load_chunk = [&](int ch, int bi) {
#pragma unroll
        for (int it = 0; it < 2; it++) {
            int f = tid + it * 512;
            int r = f >> 3, c4 = (f & 7) << 2;
            cp_async16(smem_u32(&xrb[bi][r * PXS + c4]),
                       &x[(size_t)(row0 + r) * CC + ch * KC + c4]);
        }
#pragma unroll
        for (int it = 0; it < 6; it++) {
            int f = tid + it * 512;
            if (f < 1536) {
                int r = f / 48, c4 = (f % 48) << 2;
                cp_async16(smem_u32(&whb[bi][r * PWS + c4]),
                           &g_wh[(size_t)(ch * KC + r) * 192 + c4]);
            } else {
                int f2 = f - 1536;
                int r = f2 / 48, c4 = (f2 % 48) << 2;
                cp_async16(smem_u32(&wlb[bi][r * PWS + c4]),
                           &g_wl[(size_t)(ch * KC + r) * 192 + c4]);
            }
        }
        cp_commit();
    };

    float acc[2][6][4];
#pragma unroll
    for (int mt = 0; mt < 2; mt++)
#pragma unroll
        for (int nb = 0; nb < 6; nb++)
#pragma unroll
            for (int i = 0; i < 4; i++) acc[mt][nb][i] = 0.f;

    load_chunk(0, 0);

#pragma unroll 1
    for (int ch = 0; ch < CC / KC; ch++) {
        const int bi = ch & 1;
        __syncthreads();
        if (ch + 1 < CC / KC) {
            load_chunk(ch + 1, bi ^ 1);
            cp_wait<1>();
        } else {
            cp_wait<0>();
        }
        __syncthreads();

        const uint32_t* xr = xrb[bi];
        const uint32_t* wh = whb[bi];
        const uint32_t* wl = wlb[bi];
#pragma unroll
        for (int kk = 0; kk < KC / 8; kk++) {
            uint32_t ah[2][4];
#pragma unroll
            for (int mt = 0; mt < 2; mt++) {
                int r = wr + 16 * mt;
                ah[mt][0] = f2tf(__uint_as_float(xr[(r + g) * PXS + 8 * kk + c]));
                ah[mt][1] = f2tf(__uint_as_float(xr[(r + g + 8) * PXS + 8 * kk + c]));
                ah[mt][2] = f2tf(__uint_as_float(xr[(r + g) * PXS + 8 * kk + c + 4]));
                ah[mt][3] = f2tf(__uint_as_float(xr[(r + g + 8) * PXS + 8 * kk + c + 4]));
            }
#pragma unroll
            for (int nb = 0; nb < 6; nb++) {
                int bcol = wc + 8 * nb + g;
                uint32_t bh0 = wh[(8 * kk + c) * PWS + bcol];
                uint32_t bh1 = wh[(8 * kk + c + 4) * PWS + bcol];
                uint32_t bl0 = wl[(8 * kk + c) * PWS + bcol];
                uint32_t bl1 = wl[(8 * kk + c + 4) * PWS + bcol];
#pragma unroll
                for (int mt = 0; mt < 2; mt++) {
                    mma_tf32(acc[mt][nb][0], acc[mt][nb][1], acc[mt][nb][2], acc[mt][nb][3],
                             ah[mt][0], ah[mt][1], ah[mt][2], ah[mt][3], bh0, bh1);
                    mma_tf32(acc[mt][nb][0], acc[mt][nb][1], acc[mt][nb][2], acc[mt][nb][3],
                             ah[mt][0], ah[mt][1], ah[mt][2], ah[mt][3], bl0, bl1);
                }
            }
        }
    }

    // ---- epilogue: fp16-packed stores ----
    const float qscale = rsqrtf((float)CC) * 1.44269504088896341f;
    __half* gv = (__half*)g_v;
#pragma unroll
    for (int mt = 0; mt < 2; mt++) {
#pragma unroll
        for (int nb = 0; nb < 6; nb++) {
            int colg = wc + 8 * nb + 2 * c;          // even
            int rg0 = row0 + wr + 16 * mt + g;
            int rg1 = rg0 + 8;
            float v0 = acc[mt][nb][0], v1 = acc[mt][nb][1];
            float v2 = acc[mt][nb][2], v3 = acc[mt][nb][3];
            if (colg < 64) {                  // K: [tok][head-pair permuted]
                int pp = permp(colg >> 1);
                g_k[(size_t)rg0 * 32 + pp] = packh2(v0, v1);
                g_k[(size_t)rg1 * 32 + pp] = packh2(v2, v3);
            } else if (colg < 128) {          // Q: scaled, same layout
                int pp = permp((colg - 64) >> 1);
                g_q[(size_t)rg0 * 32 + pp] = packh2(v0 * qscale, v1 * qscale);
                g_q[(size_t)rg1 * 32 + pp] = packh2(v2 * qscale, v3 * qscale);
            } else {                          // V: per-tile [head][tok-pair permuted]
                int h0 = colg - 128;
                int tile = rg0 >> 6;          // rg1 in same tile
                int t0 = rg0 & 63, t1 = rg1 & 63;
                int q0 = 2 * permp(t0 >> 1) + (t0 & 1);
                int q1 = 2 * permp(t1 >> 1) + (t1 & 1);
                size_t base = (size_t)tile * 4096;
                gv[base + (size_t)h0 * 64 + q0]       = __float2half_rn(v0);
                gv[base + (size_t)(h0 + 1) * 64 + q0] = __float2half_rn(v1);
                gv[base + (size_t)h0 * 64 + q1]       = __float2half_rn(v2);
                gv[base + (size_t)(h0 + 1) * 64 + q1] = __float2half_rn(v3);
            }
        }
    }
}

// ---------------------------------------------------------------------------
// Flash attention, fp16 m16n8k16 mma, split-KV, cp.async double-buffered K/V.
// 8 warps x 16 rows. All B-frags single LDS.64; P stays in registers.
// ---------------------------------------------------------------------------
#define PADH 40                  // u32 row stride (32 data + 8 pad), 8 mod 32
#define KVBUFH (2 * 64 * PADH)   // K+V tile per buffer, u32

__global__ __launch_bounds__(256, 2) void flash_kernel() {
    extern __shared__ uint32_t smem[];
    uint32_t (*Qs)[PADH] = (uint32_t(*)[PADH])(smem + 2 * KVBUFH);

    const int rr = NITEMS - 1 - blockIdx.x;
    const int b = rr / NITEMS_PER_B;
    const int r = rr - b * NITEMS_PER_B;
    int qb, sp;
    if (r < 8)       { qb = r;                 sp = 0; }
    else if (r < 24) { qb = 8 + (r - 8) / 2;   sp = (r - 8) & 1; }
    else if (r < 48) { qb = 16 + (r - 24) / 3; sp = (r - 24) % 3; }
    else             { qb = 24 + (r - 48) / 4; sp = (r - 48) & 3; }

    const int n_tiles = 2 * qb + 2;
    const int jb_lo = sp * SPLIT;
    const int jb_hi = min(jb_lo + SPLIT, n_tiles);

    const int tid = threadIdx.x;
    const int w = tid >> 5;
    const int lane = tid & 31;
    const int g = lane >> 2;
    const int c = lane & 3;

    auto kv_load = [&](int jb, int bi) {
        const uint32_t* Kg = g_k + (size_t)(b * TT + jb * BN) * 32;
        const uint32_t* Vg = g_v + (size_t)(b * TT + jb * BN) * 32;  // tile base
        uint32_t* Kd = smem + bi * KVBUFH;
        uint32_t* Vd = Kd + 64 * PADH;
#pragma unroll
        for (int it = 0; it < 2; it++) {
            int f = tid + it * 256;          // 0..511
            int row = f >> 3, c4 = (f & 7) << 2;
            cp_async16(smem_u32(&Kd[row * PADH + c4]), &Kg[(size_t)row * 32 + c4]);
            cp_async16(smem_u32(&Vd[row * PADH + c4]), &Vg[(size_t)row * 32 + c4]);
        }
        cp_commit();
    };

    const uint32_t* Qg = g_q + (size_t)(b * TT + qb * BM) * 32;
#pragma unroll
    for (int it = 0; it < 4; it++) {
        int f = tid + it * 256;              // 0..1023
        int row = f >> 3, c4 = (f & 7) << 2;
        cp_async16(smem_u32(&Qs[row][c4]), &Qg[(size_t)row * 32 + c4]);
    }
    cp_commit();
    kv_load(jb_lo, 0);
    cp_wait<1>();           // Q ready
    __syncthreads();

    uint32_t qf[4][4];
#pragma unroll
    for (int kk = 0; kk < 4; kk++) {
        uint2 uq0 = *(const uint2*)&Qs[16 * w + g][8 * kk + 2 * c];
        uint2 uq1 = *(const uint2*)&Qs[16 * w + g + 8][8 * kk + 2 * c];
        qf[kk][0] = uq0.x; qf[kk][2] = uq0.y;    // a0, a2
        qf[kk][1] = uq1.x; qf[kk][3] = uq1.y;    // a1, a3
    }

    float o[8][4];
#pragma unroll
    for (int nb = 0; nb < 8; nb++)
#pragma unroll
        for (int i = 0; i < 4; i++) o[nb][i] = 0.f;
    float m0 = -INFINITY, m1 = -INFINITY, l0 = 0.f, l1 = 0.f;

#pragma unroll 1
    for (int jb = jb_lo; jb < jb_hi; jb++) {
        const int bi = (jb - jb_lo) & 1;
        __syncthreads();
        if (jb + 1 < jb_hi) {
            kv_load(jb + 1, bi ^ 1);
            cp_wait<1>();
        } else {
            cp_wait<0>();
        }
        __syncthreads();

        const uint32_t (*Ks)[PADH] = (const uint32_t(*)[PADH])(smem + bi * KVBUFH);
        const uint32_t (*Vs)[PADH] = (const uint32_t(*)[PADH])(smem + bi * KVBUFH + 64 * PADH);

        // ---- S = Q K^T ----
        float s[8][4];
#pragma unroll
        for (int nb = 0; nb < 8; nb++) {
            s[nb][0] = s[nb][1] = s[nb][2] = s[nb][3] = 0.f;
#pragma unroll
            for (int kk = 0; kk < 4; kk++) {
                uint2 ub = *(const uint2*)&Ks[8 * nb + g][8 * kk + 2 * c];
                mma_f16(s[nb][0], s[nb][1], s[nb][2], s[nb][3],
                        qf[kk][0], qf[kk][1], qf[kk][2], qf[kk][3], ub.x, ub.y);
            }
        }

        if (jb >= n_tiles - 2) {              // causal mask (diagonal tiles)
            const int row0g = qb * BM + 16 * w + g;
            const int col0g = jb * BN + 2 * c;
#pragma unroll
            for (int nb = 0; nb < 8; nb++) {
                int cg = col0g + 8 * nb;
                if (cg     > row0g)     s[nb][0] = -INFINITY;
                if (cg + 1 > row0g)     s[nb][1] = -INFINITY;
                if (cg     > row0g + 8) s[nb][2] = -INFINITY;
                if (cg + 1 > row0g + 8) s[nb][3] = -INFINITY;
            }
        }

        // ---- online softmax (base-2); P kept in registers (fp32) ----
        float mx0 = -INFINITY, mx1 = -INFINITY;
#pragma unroll
        for (int nb = 0; nb < 8; nb++) {
            mx0 = fmaxf(mx0, fmaxf(s[nb][0], s[nb][1]));
            mx1 = fmaxf(mx1, fmaxf(s[nb][2], s[nb][3]));
        }
#pragma unroll
        for (int off = 1; off <= 2; off <<= 1) {
            mx0 = fmaxf(mx0, __shfl_xor_sync(0xffffffffu, mx0, off));
            mx1 = fmaxf(mx1, __shfl_xor_sync(0xffffffffu, mx1, off));
        }
        float mn0 = fmaxf(m0, mx0), mn1 = fmaxf(m1, mx1);
        float a0 = exp2f(m0 - mn0), a1 = exp2f(m1 - mn1);
        m0 = mn0; m1 = mn1;

        float rs0 = 0.f, rs1 = 0.f;
#pragma unroll
        for (int nb = 0; nb < 8; nb++) {
            float p0 = exp2f(s[nb][0] - m0);
            float p1 = exp2f(s[nb][1] - m0);
            float p2 = exp2f(s[nb][2] - m1);
            float p3 = exp2f(s[nb][3] - m1);
            rs0 += p0 + p1; rs1 += p2 + p3;
            s[nb][0] = p0; s[nb][1] = p1; s[nb][2] = p2; s[nb][3] = p3;
        }
#pragma unroll
        for (int off = 1; off <= 2; off <<= 1) {
            rs0 += __shfl_xor_sync(0xffffffffu, rs0, off);
            rs1 += __shfl_xor_sync(0xffffffffu, rs1, off);
        }
        l0 = l0 * a0 + rs0;
        l1 = l1 * a1 + rs1;
#pragma unroll
        for (int nb = 0; nb < 8; nb++) {
            o[nb][0] *= a0; o[nb][1] *= a0;
            o[nb][2] *= a1; o[nb][3] *= a1;
        }

        // ---- O += P V (P packed to fp16 A-frags from registers) ----
#pragma unroll
        for (int kt = 0; kt < 4; kt++) {
            uint32_t pa0 = packh2(s[2 * kt][0],     s[2 * kt][1]);       // row g,   k 2c..2c+1
            uint32_t pa1 = packh2(s[2 * kt][2],     s[2 * kt][3]);       // row g+8
            uint32_t pa2 = packh2(s[2 * kt + 1][0], s[2 * kt + 1][1]);   // row g,   k 2c+8..9
            uint32_t pa3 = packh2(s[2 * kt + 1][2], s[2 * kt + 1][3]);   // row g+8
#pragma unroll
            for (int nb = 0; nb < 8; nb++) {
                uint2 uv = *(const uint2*)&Vs[8 * nb + g][8 * kt + 2 * c];
                mma_f16(o[nb][0], o[nb][1], o[nb][2], o[nb][3],
                        pa0, pa1, pa2, pa3, uv.x, uv.y);
            }
        }
    }

    const int p = ((b * QB_PER_B + qb) << 2) + sp;
    float* pacc = g_pacc + (size_t)p * BM * HD;
    const int r0 = 16 * w + g;
#pragma unroll
    for (int nb = 0; nb < 8; nb++) {
        *(float2*)&pacc[(size_t)r0 * HD + 8 * nb + 2 * c]       = make_float2(o[nb][0], o[nb][1]);
        *(float2*)&pacc[(size_t)(r0 + 8) * HD + 8 * nb + 2 * c] = make_float2(o[nb][2], o[nb][3]);
    }
    if (c == 0) {
        g_pm[p * BM + r0] = m0;     g_pm[p * BM + r0 + 8] = m1;
        g_pl[p * BM + r0] = l0;     g_pl[p * BM + r0 + 8] = l1;
    }
}

// ---------------------------------------------------------------------------
// Combine split partials -> output. Grid (128, 4): block = 32 rows x 64 cols.
// ---------------------------------------------------------------------------
__global__ __launch_bounds__(256) void combine_kernel(float* __restrict__ out) {
    __shared__ float wsm[4][32];
    __shared__ float linv[32];

    const int bq = blockIdx.x;                 // 0..127
    const int b = bq >> 5;
    const int qb = bq & 31;
    const int nS = qb / 8 + 1;                 // 1..4 splits
    const int yc = blockIdx.y;                 // row chunk 0..3 (32 rows each)
    const int tid = threadIdx.x;
    const int pbase = bq << 2;

    if (tid < 32) {
        int row = yc * 32 + tid;
        float M = -INFINITY;
#pragma unroll 4
        for (int s = 0; s < nS; s++)
            M = fmaxf(M, g_pm[(pbase + s) * BM + row]);
        float L = 0.f;
#pragma unroll 4
        for (int s = 0; s < nS; s++) {
            float wgt = exp2f(g_pm[(pbase + s) * BM + row] - M);
            wsm[s][tid] = wgt;
            L += g_pl[(pbase + s) * BM + row] * wgt;
        }
        linv[tid] = 1.0f / L;
    }
    __syncthreads();

    float* og = out + ((size_t)b * TT + (size_t)qb * BM) * HD;

#pragma unroll
    for (int e = 0; e < 2; e++) {
        int f = tid + e * 256;                 // 0..511 float4 slots
        int row_l = f >> 4;                    // 0..31
        int c4 = (f & 15) << 2;                // 0..60
        int row = yc * 32 + row_l;
        size_t off = (size_t)row * HD + c4;

        float4 sum = make_float4(0.f, 0.f, 0.f, 0.f);
#pragma unroll 4
        for (int s = 0; s < nS; s++) {
            float4 v = *(const float4*)&g_pacc[(size_t)(pbase + s) * BM * HD + off];
            float wgt = wsm[s][row_l];
            sum.x += v.x * wgt;
            sum.y += v.y * wgt;
            sum.z += v.z * wgt;
            sum.w += v.w * wgt;
        }
        float li = linv[row_l];
        sum.x *= li; sum.y *= li; sum.z *= li; sum.w *= li;
        *(float4*)&og[off] = sum;
    }
}

// ---------------------------------------------------------------------------
extern "C" void kernel_launch(void* const* d_in, const int* in_sizes, int n_in,
                              void* d_out, int out_size) {
    const float* x  = (const float*)d_in[0];
    const float* Wk = (const float*)d_in[1];
    const float* Wq = (const float*)d_in[2];
    const float* Wv = (const float*)d_in[3];
    float* out = (float*)d_out;
    (void)in_sizes; (void)n_in; (void)out_size;

    const int proj_smem = (2 * XRSZ + 4 * WSZ) * (int)sizeof(uint32_t);      // 139264
    const int flash_smem = (2 * KVBUFH + 128 * PADH) * (int)sizeof(uint32_t); // 61440
    cudaFuncSetAttribute(proj_kernel,
                         cudaFuncAttributeMaxDynamicSharedMemorySize, proj_smem);
    cudaFuncSetAttribute(flash_kernel,
                         cudaFuncAttributeMaxDynamicSharedMemorySize, flash_smem);

    prep_kernel<<<96, 256>>>(Wk, Wq, Wv);
    proj_kernel<<<128, 512, proj_smem>>>(x);
    flash_kernel<<<NITEMS, 256, flash_smem>>>();
    combine_kernel<<<dim3(128, 4), 256>>>(out);
}

// round 16
// speedup vs baseline: 1.5946x; 1.2092x over previous
#include <cuda_runtime.h>
#include <cuda_fp16.h>
#include <math.h>
#include <stdint.h>

#define BB 4
#define TT 4096
#define CC 512
#define HD 64

#define BM 128           // q-tile rows per flash CTA
#define BN 64            // kv-tile rows
#define SPLIT 16         // max KV tiles per work item
#define QB_PER_B 32      // TT / BM
#define NITEMS_PER_B 80
#define NITEMS (BB * NITEMS_PER_B)   // 320

// fp16 packed storage (2 elems per u32):
// q/k: [tok][head-pair permuted]  (q pre-scaled by C^-0.5 * log2e)
// v:   per-64-tok tile, [head][tok-pair permuted]
__device__ uint32_t g_q[BB * TT * HD / 2];
__device__ uint32_t g_k[BB * TT * HD / 2];
__device__ uint32_t g_v[BB * TT * HD / 2];

// pre-packed W as fp16 pairs: [256 k-pairs][192 cols = Wk|Wq|Wv], hi + lo residual
__device__ uint32_t g_wh2[(CC / 2) * 192];
__device__ uint32_t g_wl2[(CC / 2) * 192];

// split-KV partials
__device__ float g_pacc[BB * QB_PER_B * 4 * BM * HD];
__device__ float g_pm[BB * QB_PER_B * 4 * BM];
__device__ float g_pl[BB * QB_PER_B * 4 * BM];

// pair-index permutation (32 pairs): maps (8a+c, 8a+c+4) -> (8a+2c, 8a+2c+1)
__device__ __forceinline__ int permp(int p) {
    return (p & 0x18) | ((p & 3) << 1) | ((p >> 2) & 1);
}

__device__ __forceinline__ uint32_t packh2(float lo, float hi) {
    __half2 h = __floats2half2_rn(lo, hi);
    return *(uint32_t*)&h;
}

__device__ __forceinline__ void mma_f16(float& d0, float& d1, float& d2, float& d3,
                                        uint32_t a0, uint32_t a1, uint32_t a2, uint32_t a3,
                                        uint32_t b0, uint32_t b1) {
    asm volatile(
        "mma.sync.aligned.m16n8k16.row.col.f32.f16.f16.f32 "
        "{%0,%1,%2,%3}, {%4,%5,%6,%7}, {%8,%9}, {%0,%1,%2,%3};"
        : "+f"(d0), "+f"(d1), "+f"(d2), "+f"(d3)
        : "r"(a0), "r"(a1), "r"(a2), "r"(a3), "r"(b0), "r"(b1));
}

__device__ __forceinline__ uint32_t smem_u32(const void* p) {
    return (uint32_t)__cvta_generic_to_shared(p);
}
__device__ __forceinline__ void cp_async16(uint32_t dst, const void* src) {
    asm volatile("cp.async.ca.shared.global [%0], [%1], 16;" :: "r"(dst), "l"(src));
}
__device__ __forceinline__ void cp_commit() {
    asm volatile("cp.async.commit_group;");
}
template <int N>
__device__ __forceinline__ void cp_wait() {
    asm volatile("cp.async.wait_group %0;" :: "n"(N));
}

// ---------------------------------------------------------------------------
// Prep: pack W (Wk|Wq|Wv -> [256 pairs][192]) into fp16-pair hi + lo residual.
// ---------------------------------------------------------------------------
__global__ __launch_bounds__(256) void prep_kernel(const float* __restrict__ Wk,
                                                   const float* __restrict__ Wq,
                                                   const float* __restrict__ Wv) {
    int idx = blockIdx.x * 256 + threadIdx.x;       // < 256*192
    if (idx >= (CC / 2) * 192) return;
    int p = idx / 192;
    int col = idx % 192;
    const float* src;
    int cl;
    if (col < 64)       { src = Wk; cl = col; }
    else if (col < 128) { src = Wq; cl = col - 64; }
    else                { src = Wv; cl = col - 128; }
    float v0 = src[(size_t)(2 * p) * HD + cl];
    float v1 = src[(size_t)(2 * p + 1) * HD + cl];
    __half h0 = __float2half_rn(v0);
    __half h1 = __float2half_rn(v1);
    g_wh2[idx] = packh2(__half2float(h0), __half2float(h1));
    g_wl2[idx] = packh2(v0 - __half2float(h0), v1 - __half2float(h1));
}

// ---------------------------------------------------------------------------
// Fused projection GEMM (fp16 m16n8k16, hi/lo W compensation):
// [16384x512] @ [512x192]. x rounded to fp16 at fragment load.
// ---------------------------------------------------------------------------
#define KC 32
#define PXS 40                // x raw row stride (32 data + 8 pad)
#define PW2 200               // W pair-row stride (192 data + 8 pad)
#define XRSZ (128 * PXS)      // 5120
#define WSZ2 (16 * PW2)       // 3200 (16 pair-rows per 32-k chunk)

__global__ __launch_bounds__(512, 1) void proj_kernel(const float* __restrict__ x) {
    extern __shared__ uint32_t psm[];
    uint32_t* xrb[2] = { psm, psm + XRSZ };
    uint32_t* whb[2] = { psm + 2 * XRSZ, psm + 2 * XRSZ + WSZ2 };
    uint32_t* wlb[2] = { psm + 2 * XRSZ + 2 * WSZ2, psm + 2 * XRSZ + 3 * WSZ2 };

    const int row0 = blockIdx.x * 128;
    const int tid = threadIdx.x;
    const int w = tid >> 5;
    const int lane = tid & 31;
    const int g = lane >> 2;
    const int c = lane & 3;
    const int wr = (w & 3) * 32;      // warp row base (0,32,64,96)
    const int wc = (w >> 2) * 48;     // warp col base (0,48,96,144)

    auto load_chunk = [&](int ch, int bi) {
        // x raw chunk [128 x 32]: 1024 16B
#pragma unroll
        for (int it = 0; it < 2; it++) {
            int f = tid + it * 512;
            int r = f >> 3, c4 = (f & 7) << 2;
            cp_async16(smem_u32(&xrb[bi][r * PXS + c4]),
                       &x[(size_t)(row0 + r) * CC + ch * KC + c4]);
        }
        // W hi+lo chunk [16 pairs x 192] each: 768 + 768 16B
#pragma unroll
        for (int it = 0; it < 3; it++) {
            int f = tid + it * 512;
            if (f < 768) {
                int r = f / 48, c4 = (f % 48) << 2;
                cp_async16(smem_u32(&whb[bi][r * PW2 + c4]),
                           &g_wh2[(size_t)(ch * 16 + r) * 192 + c4]);
            } else {
                int f2 = f - 768;
                int r = f2 / 48, c4 = (f2 % 48) << 2;
                cp_async16(smem_u32(&wlb[bi][r * PW2 + c4]),
                           &g_wl2[(size_t)(ch * 16 + r) * 192 + c4]);
            }
        }
        cp_commit();
    };

    float acc[2][6][4];
#pragma unroll
    for (int mt = 0; mt < 2; mt++)
#pragma unroll
        for (int nb = 0; nb < 6; nb++)
#pragma unroll
            for (int i = 0; i < 4; i++) acc[mt][nb][i] = 0.f;

    load_chunk(0, 0);

#pragma unroll 1
    for (int ch = 0; ch < CC / KC; ch++) {
        const int bi = ch & 1;
        __syncthreads();
        if (ch + 1 < CC / KC) {
            load_chunk(ch + 1, bi ^ 1);
            cp_wait<1>();
        } else {
            cp_wait<0>();
        }
        __syncthreads();

        const uint32_t* xr = xrb[bi];
        const uint32_t* wh = whb[bi];
        const uint32_t* wl = wlb[bi];
#pragma unroll
        for (int kt = 0; kt < 2; kt++) {         // two k16 steps per 32-chunk
            uint32_t a[2][4];
#pragma unroll
            for (int mt = 0; mt < 2; mt++) {
                int r = wr + 16 * mt;
                float2 x0 = *(const float2*)&xr[(r + g) * PXS + 16 * kt + 2 * c];
                float2 x1 = *(const float2*)&xr[(r + g + 8) * PXS + 16 * kt + 2 * c];
                float2 x2 = *(const float2*)&xr[(r + g) * PXS + 16 * kt + 2 * c + 8];
                float2 x3 = *(const float2*)&xr[(r + g + 8) * PXS + 16 * kt + 2 * c + 8];
                a[mt][0] = packh2(x0.x, x0.y);
                a[mt][1] = packh2(x1.x, x1.y);
                a[mt][2] = packh2(x2.x, x2.y);
                a[mt][3] = packh2(x3.x, x3.y);
            }
#pragma unroll
            for (int nb = 0; nb < 6; nb++) {
                int bcol = wc + 8 * nb + g;
                uint32_t bh0 = wh[(8 * kt + c) * PW2 + bcol];
                uint32_t bh1 = wh[(8 * kt + c + 4) * PW2 + bcol];
                uint32_t bl0 = wl[(8 * kt + c) * PW2 + bcol];
                uint32_t bl1 = wl[(8 * kt + c + 4) * PW2 + bcol];
#pragma unroll
                for (int mt = 0; mt < 2; mt++) {
                    mma_f16(acc[mt][nb][0], acc[mt][nb][1], acc[mt][nb][2], acc[mt][nb][3],
                            a[mt][0], a[mt][1], a[mt][2], a[mt][3], bh0, bh1);
                    mma_f16(acc[mt][nb][0], acc[mt][nb][1], acc[mt][nb][2], acc[mt][nb][3],
                            a[mt][0], a[mt][1], a[mt][2], a[mt][3], bl0, bl1);
                }
            }
        }
    }

    // ---- epilogue: fp16-packed stores (same as R15) ----
    const float qscale = rsqrtf((float)CC) * 1.44269504088896341f;
    __half* gv = (__half*)g_v;
#pragma unroll
    for (int mt = 0; mt < 2; mt++) {
#pragma unroll
        for (int nb = 0; nb < 6; nb++) {
            int colg = wc + 8 * nb + 2 * c;          // even
            int rg0 = row0 + wr + 16 * mt + g;
            int rg1 = rg0 + 8;
            float v0 = acc[mt][nb][0], v1 = acc[mt][nb][1];
            float v2 = acc[mt][nb][2], v3 = acc[mt][nb][3];
            if (colg < 64) {                  // K: [tok][head-pair permuted]
                int pp = permp(colg >> 1);
                g_k[(size_t)rg0 * 32 + pp] = packh2(v0, v1);
                g_k[(size_t)rg1 * 32 + pp] = packh2(v2, v3);
            } else if (colg < 128) {          // Q: scaled, same layout
                int pp = permp((colg - 64) >> 1);
                g_q[(size_t)rg0 * 32 + pp] = packh2(v0 * qscale, v1 * qscale);
                g_q[(size_t)rg1 * 32 + pp] = packh2(v2 * qscale, v3 * qscale);
            } else {                          // V: per-tile [head][tok-pair permuted]
                int h0 = colg - 128;
                int tile = rg0 >> 6;          // rg1 in same tile
                int t0 = rg0 & 63, t1 = rg1 & 63;
                int q0 = 2 * permp(t0 >> 1) + (t0 & 1);
                int q1 = 2 * permp(t1 >> 1) + (t1 & 1);
                size_t base = (size_t)tile * 4096;
                gv[base + (size_t)h0 * 64 + q0]       = __float2half_rn(v0);
                gv[base + (size_t)(h0 + 1) * 64 + q0] = __float2half_rn(v1);
                gv[base + (size_t)h0 * 64 + q1]       = __float2half_rn(v2);
                gv[base + (size_t)(h0 + 1) * 64 + q1] = __float2half_rn(v3);
            }
        }
    }
}

// ---------------------------------------------------------------------------
// Flash attention, fp16 m16n8k16 mma, split-KV, cp.async double-buffered K/V.
// 8 warps x 16 rows. All B-frags single LDS.64; P stays in registers.
// ---------------------------------------------------------------------------
#define PADH 40                  // u32 row stride (32 data + 8 pad), 8 mod 32
#define KVBUFH (2 * 64 * PADH)   // K+V tile per buffer, u32

__global__ __launch_bounds__(256, 2) void flash_kernel() {
    extern __shared__ uint32_t smem[];
    uint32_t (*Qs)[PADH] = (uint32_t(*)[PADH])(smem + 2 * KVBUFH);

    const int rr = NITEMS - 1 - blockIdx.x;
    const int b = rr / NITEMS_PER_B;
    const int r = rr - b * NITEMS_PER_B;
    int qb, sp;
    if (r < 8)       { qb = r;                 sp = 0; }
    else if (r < 24) { qb = 8 + (r - 8) / 2;   sp = (r - 8) & 1; }
    else if (r < 48) { qb = 16 + (r - 24) / 3; sp = (r - 24) % 3; }
    else             { qb = 24 + (r - 48) / 4; sp = (r - 48) & 3; }

    const int n_tiles = 2 * qb + 2;
    const int jb_lo = sp * SPLIT;
    const int jb_hi = min(jb_lo + SPLIT, n_tiles);

    const int tid = threadIdx.x;
    const int w = tid >> 5;
    const int lane = tid & 31;
    const int g = lane >> 2;
    const int c = lane & 3;

    auto kv_load = [&](int jb, int bi) {
        const uint32_t* Kg = g_k + (size_t)(b * TT + jb * BN) * 32;
        const uint32_t* Vg = g_v + (size_t)(b * TT + jb * BN) * 32;  // tile base
        uint32_t* Kd = smem + bi * KVBUFH;
        uint32_t* Vd = Kd + 64 * PADH;
#pragma unroll
        for (int it = 0; it < 2; it++) {
            int f = tid + it * 256;          // 0..511
            int row = f >> 3, c4 = (f & 7) << 2;
            cp_async16(smem_u32(&Kd[row * PADH + c4]), &Kg[(size_t)row * 32 + c4]);
            cp_async16(smem_u32(&Vd[row * PADH + c4]), &Vg[(size_t)row * 32 + c4]);
        }
        cp_commit();
    };

    const uint32_t* Qg = g_q + (size_t)(b * TT + qb * BM) * 32;
#pragma unroll
    for (int it = 0; it < 4; it++) {
        int f = tid + it * 256;              // 0..1023
        int row = f >> 3, c4 = (f & 7) << 2;
        cp_async16(smem_u32(&Qs[row][c4]), &Qg[(size_t)row * 32 + c4]);
    }
    cp_commit();
    kv_load(jb_lo, 0);
    cp_wait<1>();           // Q ready
    __syncthreads();

    uint32_t qf[4][4];
#pragma unroll
    for (int kk = 0; kk < 4; kk++) {
        uint2 uq0 = *(const uint2*)&Qs[16 * w + g][8 * kk + 2 * c];
        uint2 uq1 = *(const uint2*)&Qs[16 * w + g + 8][8 * kk + 2 * c];
        qf[kk][0] = uq0.x; qf[kk][2] = uq0.y;    // a0, a2
        qf[kk][1] = uq1.x; qf[kk][3] = uq1.y;    // a1, a3
    }

    float o[8][4];
#pragma unroll
    for (int nb = 0; nb < 8; nb++)
#pragma unroll
        for (int i = 0; i < 4; i++) o[nb][i] = 0.f;
    float m0 = -INFINITY, m1 = -INFINITY, l0 = 0.f, l1 = 0.f;

#pragma unroll 1
    for (int jb = jb_lo; jb < jb_hi; jb++) {
        const int bi = (jb - jb_lo) & 1;
        __syncthreads();
        if (jb + 1 < jb_hi) {
            kv_load(jb + 1, bi ^ 1);
            cp_wait<1>();
        } else {
            cp_wait<0>();
        }
        __syncthreads();

        const uint32_t (*Ks)[PADH] = (const uint32_t(*)[PADH])(smem + bi * KVBUFH);
        const uint32_t (*Vs)[PADH] = (const uint32_t(*)[PADH])(smem + bi * KVBUFH + 64 * PADH);

        // ---- S = Q K^T ----
        float s[8][4];
#pragma unroll
        for (int nb = 0; nb < 8; nb++) {
            s[nb][0] = s[nb][1] = s[nb][2] = s[nb][3] = 0.f;
#pragma unroll
            for (int kk = 0; kk < 4; kk++) {
                uint2 ub = *(const uint2*)&Ks[8 * nb + g][8 * kk + 2 * c];
                mma_f16(s[nb][0], s[nb][1], s[nb][2], s[nb][3],
                        qf[kk][0], qf[kk][1], qf[kk][2], qf[kk][3], ub.x, ub.y);
            }
        }

        if (jb >= n_tiles - 2) {              // causal mask (diagonal tiles)
            const int row0g = qb * BM + 16 * w + g;
            const int col0g = jb * BN + 2 * c;
#pragma unroll
            for (int nb = 0; nb < 8; nb++) {
                int cg = col0g + 8 * nb;
                if (cg     > row0g)     s[nb][0] = -INFINITY;
                if (cg + 1 > row0g)     s[nb][1] = -INFINITY;
                if (cg     > row0g + 8) s[nb][2] = -INFINITY;
                if (cg + 1 > row0g + 8) s[nb][3] = -INFINITY;
            }
        }

        // ---- online softmax (base-2); P kept in registers (fp32) ----
        float mx0 = -INFINITY, mx1 = -INFINITY;
#pragma unroll
        for (int nb = 0; nb < 8; nb++) {
            mx0 = fmaxf(mx0, fmaxf(s[nb][0], s[nb][1]));
            mx1 = fmaxf(mx1, fmaxf(s[nb][2], s[nb][3]));
        }
#pragma unroll
        for (int off = 1; off <= 2; off <<= 1) {
            mx0 = fmaxf(mx0, __shfl_xor_sync(0xffffffffu, mx0, off));
            mx1 = fmaxf(mx1, __shfl_xor_sync(0xffffffffu, mx1, off));
        }
        float mn0 = fmaxf(m0, mx0), mn1 = fmaxf(m1, mx1);
        float a0 = exp2f(m0 - mn0), a1 = exp2f(m1 - mn1);
        m0 = mn0; m1 = mn1;

        float rs0 = 0.f, rs1 = 0.f;
#pragma unroll
        for (int nb = 0; nb < 8; nb++) {
            float p0 = exp2f(s[nb][0] - m0);
            float p1 = exp2f(s[nb][1] - m0);
            float p2 = exp2f(s[nb][2] - m1);
            float p3 = exp2f(s[nb][3] - m1);
            rs0 += p0 + p1; rs1 += p2 + p3;
            s[nb][0] = p0; s[nb][1] = p1; s[nb][2] = p2; s[nb][3] = p3;
        }
#pragma unroll
        for (int off = 1; off <= 2; off <<= 1) {
            rs0 += __shfl_xor_sync(0xffffffffu, rs0, off);
            rs1 += __shfl_xor_sync(0xffffffffu, rs1, off);
        }
        l0 = l0 * a0 + rs0;
        l1 = l1 * a1 + rs1;
#pragma unroll
        for (int nb = 0; nb < 8; nb++) {
            o[nb][0] *= a0; o[nb][1] *= a0;
            o[nb][2] *= a1; o[nb][3] *= a1;
        }

        // ---- O += P V (P packed to fp16 A-frags from registers) ----
#pragma unroll
        for (int kt = 0; kt < 4; kt++) {
            uint32_t pa0 = packh2(s[2 * kt][0],     s[2 * kt][1]);
            uint32_t pa1 = packh2(s[2 * kt][2],     s[2 * kt][3]);
            uint32_t pa2 = packh2(s[2 * kt + 1][0], s[2 * kt + 1][1]);
            uint32_t pa3 = packh2(s[2 * kt + 1][2], s[2 * kt + 1][3]);
#pragma unroll
            for (int nb = 0; nb < 8; nb++) {
                uint2 uv = *(const uint2*)&Vs[8 * nb + g][8 * kt + 2 * c];
                mma_f16(o[nb][0], o[nb][1], o[nb][2], o[nb][3],
                        pa0, pa1, pa2, pa3, uv.x, uv.y);
            }
        }
    }

    const int p = ((b * QB_PER_B + qb) << 2) + sp;
    float* pacc = g_pacc + (size_t)p * BM * HD;
    const int r0 = 16 * w + g;
#pragma unroll
    for (int nb = 0; nb < 8; nb++) {
        *(float2*)&pacc[(size_t)r0 * HD + 8 * nb + 2 * c]       = make_float2(o[nb][0], o[nb][1]);
        *(float2*)&pacc[(size_t)(r0 + 8) * HD + 8 * nb + 2 * c] = make_float2(o[nb][2], o[nb][3]);
    }
    if (c == 0) {
        g_pm[p * BM + r0] = m0;     g_pm[p * BM + r0 + 8] = m1;
        g_pl[p * BM + r0] = l0;     g_pl[p * BM + r0 + 8] = l1;
    }
}

// ---------------------------------------------------------------------------
// Combine split partials -> output. Grid (128, 4): block = 32 rows x 64 cols.
// ---------------------------------------------------------------------------
__global__ __launch_bounds__(256) void combine_kernel(float* __restrict__ out) {
    __shared__ float wsm[4][32];
    __shared__ float linv[32];

    const int bq = blockIdx.x;                 // 0..127
    const int b = bq >> 5;
    const int qb = bq & 31;
    const int nS = qb / 8 + 1;                 // 1..4 splits
    const int yc = blockIdx.y;                 // row chunk 0..3 (32 rows each)
    const int tid = threadIdx.x;
    const int pbase = bq << 2;

    if (tid < 32) {
        int row = yc * 32 + tid;
        float M = -INFINITY;
#pragma unroll 4
        for (int s = 0; s < nS; s++)
            M = fmaxf(M, g_pm[(pbase + s) * BM + row]);
        float L = 0.f;
#pragma unroll 4
        for (int s = 0; s < nS; s++) {
            float wgt = exp2f(g_pm[(pbase + s) * BM + row] - M);
            wsm[s][tid] = wgt;
            L += g_pl[(pbase + s) * BM + row] * wgt;
        }
        linv[tid] = 1.0f / L;
    }
    __syncthreads();

    float* og = out + ((size_t)b * TT + (size_t)qb * BM) * HD;

#pragma unroll
    for (int e = 0; e < 2; e++) {
        int f = tid + e * 256;                 // 0..511 float4 slots
        int row_l = f >> 4;                    // 0..31
        int c4 = (f & 15) << 2;                // 0..60
        int row = yc * 32 + row_l;
        size_t off = (size_t)row * HD + c4;

        float4 sum = make_float4(0.f, 0.f, 0.f, 0.f);
#pragma unroll 4
        for (int s = 0; s < nS; s++) {
            float4 v = *(const float4*)&g_pacc[(size_t)(pbase + s) * BM * HD + off];
            float wgt = wsm[s][row_l];
            sum.x += v.x * wgt;
            sum.y += v.y * wgt;
            sum.z += v.z * wgt;
            sum.w += v.w * wgt;
        }
        float li = linv[row_l];
        sum.x *= li; sum.y *= li; sum.z *= li; sum.w *= li;
        *(float4*)&og[off] = sum;
    }
}

// ---------------------------------------------------------------------------
extern "C" void kernel_launch(void* const* d_in, const int* in_sizes, int n_in,
                              void* d_out, int out_size) {
    const float* x  = (const float*)d_in[0];
    const float* Wk = (const float*)d_in[1];
    const float* Wq = (const float*)d_in[2];
    const float* Wv = (const float*)d_in[3];
    float* out = (float*)d_out;
    (void)in_sizes; (void)n_in; (void)out_size;

    const int proj_smem = (2 * XRSZ + 4 * WSZ2) * (int)sizeof(uint32_t);      // 92160
    const int flash_smem = (2 * KVBUFH + 128 * PADH) * (int)sizeof(uint32_t); // 61440
    cudaFuncSetAttribute(proj_kernel,
                         cudaFuncAttributeMaxDynamicSharedMemorySize, proj_smem);
    cudaFuncSetAttribute(flash_kernel,
                         cudaFuncAttributeMaxDynamicSharedMemorySize, flash_smem);

    prep_kernel<<<192, 256>>>(Wk, Wq, Wv);
    proj_kernel<<<128, 512, proj_smem>>>(x);
    flash_kernel<<<NITEMS, 256, flash_smem>>>();
    combine_kernel<<<dim3(128, 4), 256>>>(out);
}